// round 16
// baseline (speedup 1.0000x reference)
#include <cuda_runtime.h>
#include <cuda_bf16.h>
#include <cstdint>

#define NN 50000
#define EE 800000
#define DD 256
#define LL 3
#define GG 512

#if defined(__CUDA_ARCH_FEAT_SM103_ALL) || defined(__CUDA_ARCH_FEAT_SM100_ALL) || \
    defined(__CUDA_ARCH_FEAT_SM101_ALL) || defined(__CUDA_ARCH_SPECIFIC__)
#define HAS_TCGEN05 1
#else
#define HAS_TCGEN05 0
#endif

// ==================== PTX helpers (sm_103a-only) ====================
#if HAS_TCGEN05
__device__ __forceinline__ uint32_t smem_to_u32(const void* p) {
    uint32_t a;
    asm("{ .reg .u64 t; cvta.to.shared.u64 t, %1; cvt.u32.u64 %0, t; }" : "=r"(a) : "l"(p));
    return a;
}
__device__ __forceinline__ uint32_t elect_one_pred() {
    uint32_t pred;
    asm volatile("{\n\t.reg .pred p;\n\telect.sync _|p, 0xFFFFFFFF;\n\tselp.b32 %0, 1, 0, p;\n\t}" : "=r"(pred));
    return pred;
}
#define MBARRIER_INIT(addr, cnt) \
    asm volatile("mbarrier.init.shared.b64 [%0], %1;" :: "r"((uint32_t)(addr)), "r"((uint32_t)(cnt)) : "memory")
#define MBARRIER_WAIT_PARITY(mbar_smem_addr, phase_parity) do { \
    uint32_t _mbar = (uint32_t)(mbar_smem_addr); \
    uint32_t _parity = (uint32_t)(phase_parity); \
    uint32_t _done; \
    asm volatile("{\n\t.reg .pred p;\n\t" \
        "mbarrier.try_wait.parity.acquire.cta.shared::cta.b64 p, [%1], %2;\n\t" \
        "selp.b32 %0, 1, 0, p;\n\t}" \
        : "=r"(_done) : "r"(_mbar), "r"(_parity) : "memory"); \
    if (!_done) { \
        asm volatile("{\n\t.reg .pred P1;\n\t" \
            "WAIT_LOOP_%=:\n\t" \
            "mbarrier.try_wait.parity.acquire.cta.shared::cta.b64 P1, [%0], %1, 0x989680;\n\t" \
            "@P1 bra.uni WAIT_DONE_%=;\n\t" \
            "bra.uni WAIT_LOOP_%=;\n\t" \
            "WAIT_DONE_%=:\n\t}" \
            :: "r"(_mbar), "r"(_parity) : "memory"); \
    } \
} while(0)
#define TCGEN05_ALLOC(smem_result_addr, nCols) \
    asm volatile("tcgen05.alloc.cta_group::1.sync.aligned.shared::cta.b32 [%0], %1;" \
        :: "r"((uint32_t)(smem_result_addr)), "r"((uint32_t)(nCols)) : "memory")
#define TCGEN05_DEALLOC(tmem_addr, nCols) \
    asm volatile("tcgen05.dealloc.cta_group::1.sync.aligned.b32 %0, %1;" :: "r"(tmem_addr), "r"((uint32_t)(nCols)))
#define TCGEN05_RELINQUISH() \
    asm volatile("tcgen05.relinquish_alloc_permit.cta_group::1.sync.aligned;")
#define TCGEN05_COMMIT(mbar_smem_addr) \
    asm volatile("tcgen05.commit.cta_group::1.mbarrier::arrive::one.shared::cluster.b64 [%0];" \
        :: "r"((uint32_t)(mbar_smem_addr)) : "memory")
#define TCGEN05_WAIT_LD() asm volatile("tcgen05.wait::ld.sync.aligned;" ::: "memory")
#define TCGEN05_FENCE_AFTER() asm volatile("tcgen05.fence::after_thread_sync;" ::: "memory")
#define FENCE_PROXY_ASYNC_SHARED_CTA() asm volatile("fence.proxy.async.shared::cta;" ::: "memory")
#define TCGEN05_LD_32X32B_X32(r, tmem_addr) \
    asm volatile("tcgen05.ld.sync.aligned.32x32b.x32.b32 " \
        "{%0, %1, %2, %3, %4, %5, %6, %7, %8, %9, %10, %11, %12, %13, %14, %15, " \
        " %16, %17, %18, %19, %20, %21, %22, %23, %24, %25, %26, %27, %28, %29, %30, %31}, [%32];" \
        : "=r"((r)[0]),  "=r"((r)[1]),  "=r"((r)[2]),  "=r"((r)[3]), \
          "=r"((r)[4]),  "=r"((r)[5]),  "=r"((r)[6]),  "=r"((r)[7]), \
          "=r"((r)[8]),  "=r"((r)[9]),  "=r"((r)[10]), "=r"((r)[11]), \
          "=r"((r)[12]), "=r"((r)[13]), "=r"((r)[14]), "=r"((r)[15]), \
          "=r"((r)[16]), "=r"((r)[17]), "=r"((r)[18]), "=r"((r)[19]), \
          "=r"((r)[20]), "=r"((r)[21]), "=r"((r)[22]), "=r"((r)[23]), \
          "=r"((r)[24]), "=r"((r)[25]), "=r"((r)[26]), "=r"((r)[27]), \
          "=r"((r)[28]), "=r"((r)[29]), "=r"((r)[30]), "=r"((r)[31]) \
        : "r"(tmem_addr))

static constexpr uint64_t SMEM_DESC_BASE_SW128 =
    (uint64_t(2) << 61) | (uint64_t(1) << 46) | (uint64_t(64) << 32) | (uint64_t(1) << 16);
#define MAKE_SMEM_DESC(base_addr) (SMEM_DESC_BASE_SW128 | ((uint64_t)((base_addr) >> 4) & 0x3FFF))

__device__ __forceinline__ void mma_f16_ss(uint32_t d, uint64_t a, uint64_t b, uint32_t idesc, int en) {
    asm volatile("{\n\t.reg .pred p;\n\tsetp.ne.u32 p, %4, 0;\n\t"
        "tcgen05.mma.cta_group::1.kind::f16 [%0], %1, %2, %3, {%5, %5, %5, %5}, p;\n\t}"
        :: "r"(d), "l"(a), "l"(b), "r"(idesc), "r"((uint32_t)en), "r"(0u) : "memory");
}

static constexpr uint32_t GEMM_IDESC =
    (1u << 4) | (1u << 7) | (1u << 10) | ((256u / 8) << 17) | ((128u / 16) << 24);
#endif // HAS_TCGEN05

#define SMEM_SWIZZLE_128B(byte_offset) ((byte_offset) ^ (((byte_offset) >> 3) & 0x70))

// ==================== scratch ====================
__device__ __align__(256) __nv_bfloat16 g_agg_hi[NN * DD];
__device__ __align__(256) __nv_bfloat16 g_agg_lo[NN * DD];
__device__ __align__(256) __nv_bfloat16 g_h_hi[NN * DD];   // compact bf16 copy of current h (L2-resident)
__device__ __align__(256) __nv_bfloat16 g_h_lo[NN * DD];
__device__ __align__(256) __nv_bfloat16 g_w1_hi[LL * DD * DD];   // transposed [l][n][k]
__device__ __align__(256) __nv_bfloat16 g_w1_lo[LL * DD * DD];
__device__ __align__(256) __nv_bfloat16 g_w2_hi[LL * DD * DD];
__device__ __align__(256) __nv_bfloat16 g_w2_lo[LL * DD * DD];
__device__ int g_deg[NN];
__device__ int g_cursor[NN];
__device__ int g_rowstart[NN + 1];
__device__ int g_esrc[EE];
__device__ int g_gstart[GG + 1];

// ==================== CSR build ====================
__global__ void count_kernel(const int* __restrict__ ei) {
    int e = blockIdx.x * blockDim.x + threadIdx.x;
    if (e < EE) atomicAdd(&g_deg[ei[EE + e]], 1);
}
// scan also initializes g_cursor (folds the old memcpy)
__global__ void scan_kernel() {
    __shared__ int partials[1024];
    const int n = NN;
    int tid = threadIdx.x;
    int chunk = (n + 1023) / 1024;
    int beg = tid * chunk;
    int end = beg + chunk; if (end > n) end = n;
    int sum = 0;
    for (int i = beg; i < end; i++) sum += g_deg[i];
    partials[tid] = sum;
    __syncthreads();
    for (int off = 1; off < 1024; off <<= 1) {
        int v = 0;
        if (tid >= off) v = partials[tid - off];
        __syncthreads();
        partials[tid] += v;
        __syncthreads();
    }
    int run = (tid == 0) ? 0 : partials[tid - 1];
    for (int i = beg; i < end; i++) {
        g_rowstart[i] = run;
        g_cursor[i] = run;
        run += g_deg[i];
    }
    if (tid == 0) g_rowstart[n] = EE;
}
__global__ void fill_kernel(const int* __restrict__ ei) {
    int e = blockIdx.x * blockDim.x + threadIdx.x;
    if (e < EE) {
        int dst = ei[EE + e];
        int pos = atomicAdd(&g_cursor[dst], 1);
        g_esrc[pos] = ei[e];
    }
}

// ==================== weight prep: transpose + bf16 split ====================
__global__ void prep_weights(const float* __restrict__ Ws1, const float* __restrict__ Ws2) {
    int i = blockIdx.x * blockDim.x + threadIdx.x;
    if (i >= LL * DD * DD) return;
    int l = i >> 16;
    int r = i & 65535;
    int n = r >> 8;
    int k = r & 255;
    float w1 = Ws1[l * 65536 + k * 256 + n];
    __nv_bfloat16 h1 = __float2bfloat16(w1);
    g_w1_hi[i] = h1;
    g_w1_lo[i] = __float2bfloat16(w1 - __bfloat162float(h1));
    float w2 = Ws2[l * 65536 + k * 256 + n];
    __nv_bfloat16 h2 = __float2bfloat16(w2);
    g_w2_hi[i] = h2;
    g_w2_lo[i] = __float2bfloat16(w2 - __bfloat162float(h2));
}

// ==================== aggregation -> bf16 hi/lo ====================
__device__ __forceinline__ uint32_t pack_hi2(float a, float b, uint32_t& lo_out) {
    __nv_bfloat16 ha = __float2bfloat16(a);
    __nv_bfloat16 hb = __float2bfloat16(b);
    __nv_bfloat16 la = __float2bfloat16(a - __bfloat162float(ha));
    __nv_bfloat16 lb = __float2bfloat16(b - __bfloat162float(hb));
    lo_out = (uint32_t)__bfloat16_as_ushort(la) | ((uint32_t)__bfloat16_as_ushort(lb) << 16);
    return (uint32_t)__bfloat16_as_ushort(ha) | ((uint32_t)__bfloat16_as_ushort(hb) << 16);
}

// layer-1 aggregate: reads fp32 x (row stride 256)
__global__ __launch_bounds__(256) void aggregate_kernel(const float* __restrict__ h) {
    int node = (blockIdx.x * blockDim.x + threadIdx.x) >> 5;
    if (node >= NN) return;
    int lane = threadIdx.x & 31;
    int beg = g_rowstart[node];
    int end = g_rowstart[node + 1];
    int d0 = lane * 4;
    int d1 = 128 + lane * 4;
    float4 acc0 = make_float4(0.f, 0.f, 0.f, 0.f);
    float4 acc1 = make_float4(0.f, 0.f, 0.f, 0.f);
    for (int e = beg; e < end; e++) {
        int s = __ldg(&g_esrc[e]);
        const float* hs = h + (long)s * DD;
        float4 a = *(const float4*)(hs + d0);
        float4 b = *(const float4*)(hs + d1);
        acc0.x += a.x; acc0.y += a.y; acc0.z += a.z; acc0.w += a.w;
        acc1.x += b.x; acc1.y += b.y; acc1.z += b.z; acc1.w += b.w;
    }
    const float* hn = h + (long)node * DD;
    float4 a = *(const float4*)(hn + d0);
    float4 b = *(const float4*)(hn + d1);
    acc0.x += a.x; acc0.y += a.y; acc0.z += a.z; acc0.w += a.w;
    acc1.x += b.x; acc1.y += b.y; acc1.z += b.z; acc1.w += b.w;

    uint32_t l01, l23, m01, m23;
    uint32_t h01 = pack_hi2(acc0.x, acc0.y, l01);
    uint32_t h23 = pack_hi2(acc0.z, acc0.w, l23);
    uint32_t i01 = pack_hi2(acc1.x, acc1.y, m01);
    uint32_t i23 = pack_hi2(acc1.z, acc1.w, m23);
    __nv_bfloat16* oh = g_agg_hi + (long)node * DD;
    __nv_bfloat16* ol = g_agg_lo + (long)node * DD;
    *(uint2*)(oh + d0) = make_uint2(h01, h23);
    *(uint2*)(ol + d0) = make_uint2(l01, l23);
    *(uint2*)(oh + d1) = make_uint2(i01, i23);
    *(uint2*)(ol + d1) = make_uint2(m01, m23);
}

// layers 2..L aggregate: reads compact bf16 hi/lo h copy (51MB, L2-resident)
__device__ __forceinline__ void acc_bf16x2(float& a, float& b, uint32_t hh, uint32_t ll) {
    float2 fh = __bfloat1622float2(*reinterpret_cast<__nv_bfloat162*>(&hh));
    float2 fl = __bfloat1622float2(*reinterpret_cast<__nv_bfloat162*>(&ll));
    a += fh.x + fl.x;
    b += fh.y + fl.y;
}

__global__ __launch_bounds__(256) void aggregate_bf16_kernel() {
    int node = (blockIdx.x * blockDim.x + threadIdx.x) >> 5;
    if (node >= NN) return;
    int lane = threadIdx.x & 31;
    int beg = g_rowstart[node];
    int end = g_rowstart[node + 1];
    int d0 = lane * 4;
    int d1 = 128 + lane * 4;
    float4 acc0 = make_float4(0.f, 0.f, 0.f, 0.f);
    float4 acc1 = make_float4(0.f, 0.f, 0.f, 0.f);
    for (int e = beg; e <= end; e++) {
        int s = (e < end) ? __ldg(&g_esrc[e]) : node;   // final iter adds self term
        const __nv_bfloat16* hh = g_h_hi + (long)s * DD;
        const __nv_bfloat16* hl = g_h_lo + (long)s * DD;
        uint2 vh0 = *(const uint2*)(hh + d0);
        uint2 vl0 = *(const uint2*)(hl + d0);
        uint2 vh1 = *(const uint2*)(hh + d1);
        uint2 vl1 = *(const uint2*)(hl + d1);
        acc_bf16x2(acc0.x, acc0.y, vh0.x, vl0.x);
        acc_bf16x2(acc0.z, acc0.w, vh0.y, vl0.y);
        acc_bf16x2(acc1.x, acc1.y, vh1.x, vl1.x);
        acc_bf16x2(acc1.z, acc1.w, vh1.y, vl1.y);
    }
    uint32_t l01, l23, m01, m23;
    uint32_t h01 = pack_hi2(acc0.x, acc0.y, l01);
    uint32_t h23 = pack_hi2(acc0.z, acc0.w, l23);
    uint32_t i01 = pack_hi2(acc1.x, acc1.y, m01);
    uint32_t i23 = pack_hi2(acc1.z, acc1.w, m23);
    __nv_bfloat16* oh = g_agg_hi + (long)node * DD;
    __nv_bfloat16* ol = g_agg_lo + (long)node * DD;
    *(uint2*)(oh + d0) = make_uint2(h01, h23);
    *(uint2*)(ol + d0) = make_uint2(l01, l23);
    *(uint2*)(oh + d1) = make_uint2(i01, i23);
    *(uint2*)(ol + d1) = make_uint2(m01, m23);
}

// ==================== fused MLP: out = relu(relu(A@W1+b1)@W2+b2) ====================
#define REL_TM     0
#define REL_MBAR0  8
#define REL_MBAR1  16
#define STG_BASE   1024
#define STG_BYTES  98304
#define OFF_AH     0
#define OFF_AL     16384
#define OFF_BH     32768
#define OFF_BL     65536
#define OFF_A2H    0
#define OFF_A2L    65536
#define OFF_W2H    131072
#define OFF_W2L    163840
#define MLP_SMEM_BYTES (STG_BASE + 2 * STG_BYTES + 1024)

__global__ __launch_bounds__(256, 1) __cluster_dims__(1, 1, 1)
void mlp_tc(const __nv_bfloat16* __restrict__ Ahi, const __nv_bfloat16* __restrict__ Alo,
            const __nv_bfloat16* __restrict__ W1hi, const __nv_bfloat16* __restrict__ W1lo,
            const float* __restrict__ b1,
            const __nv_bfloat16* __restrict__ W2hi, const __nv_bfloat16* __restrict__ W2lo,
            const float* __restrict__ b2,
            float* __restrict__ outF, int ldc, int M)
{
#if HAS_TCGEN05
    extern __shared__ char smem_raw[];
    uint32_t sraw = smem_to_u32(smem_raw);
    uint32_t sb = (sraw + 1023u) & ~1023u;
    char* smem = smem_raw + (sb - sraw);

    int tid = threadIdx.x;
    int rowBase = blockIdx.x * 128;
    int wg = tid >> 7;
    int wr = tid & 127;
    int m = rowBase + wr;
    int colWG = wg << 7;

    if (tid < 32) {
        TCGEN05_ALLOC(sb + REL_TM, 512);
        TCGEN05_RELINQUISH();
    }
    if (tid == 0) {
        MBARRIER_INIT(sb + REL_MBAR0, 1);
        MBARRIER_INIT(sb + REL_MBAR1, 1);
    }
    __syncthreads();
    uint32_t tm;
    asm volatile("ld.shared.b32 %0, [%1];" : "=r"(tm) : "r"(sb + REL_TM));

    // ---------- Phase 1 ----------
    for (int c = 0; c < 4; c++) {
        int st = c & 1;
        uint32_t stage = sb + STG_BASE + (uint32_t)st * STG_BYTES;
        char* sm = smem + STG_BASE + st * STG_BYTES;
        uint32_t mbar = sb + (st ? REL_MBAR1 : REL_MBAR0);
        int k0 = c * 64;

        if (c >= 2) MBARRIER_WAIT_PARITY(mbar, 0);

        for (int i = tid; i < 128 * 8; i += 256) {
            int r = i >> 3, q = i & 7;
            uint32_t sw = SMEM_SWIZZLE_128B((uint32_t)(r * 128 + q * 16));
            uint4 vh = make_uint4(0, 0, 0, 0), vl = make_uint4(0, 0, 0, 0);
            int gr = rowBase + r;
            if (gr < M) {
                vh = *(const uint4*)(Ahi + (size_t)gr * 256 + k0 + q * 8);
                vl = *(const uint4*)(Alo + (size_t)gr * 256 + k0 + q * 8);
            }
            *(uint4*)(sm + OFF_AH + sw) = vh;
            *(uint4*)(sm + OFF_AL + sw) = vl;
        }
        for (int i = tid; i < 256 * 8; i += 256) {
            int n = i >> 3, q = i & 7;
            uint32_t sw = SMEM_SWIZZLE_128B((uint32_t)(n * 128 + q * 16));
            *(uint4*)(sm + OFF_BH + sw) = *(const uint4*)(W1hi + (size_t)n * 256 + k0 + q * 8);
            *(uint4*)(sm + OFF_BL + sw) = *(const uint4*)(W1lo + (size_t)n * 256 + k0 + q * 8);
        }
        FENCE_PROXY_ASYNC_SHARED_CTA();
        __syncthreads();

        if (tid < 32 && elect_one_pred()) {
            uint64_t dAH = MAKE_SMEM_DESC(stage + OFF_AH);
            uint64_t dAL = MAKE_SMEM_DESC(stage + OFF_AL);
            uint64_t dBH = MAKE_SMEM_DESC(stage + OFF_BH);
            uint64_t dBL = MAKE_SMEM_DESC(stage + OFF_BL);
            #pragma unroll
            for (int s = 0; s < 4; s++) {
                uint64_t off = (uint64_t)(2 * s);
                mma_f16_ss(tm, dAH + off, dBH + off, GEMM_IDESC, !(c == 0 && s == 0));
                mma_f16_ss(tm, dAL + off, dBH + off, GEMM_IDESC, 1);
                mma_f16_ss(tm, dAH + off, dBL + off, GEMM_IDESC, 1);
            }
            TCGEN05_COMMIT(mbar);
        }
    }

    // ---------- Epilogue 1: t -> SMEM A2 (bf16 split) ----------
    MBARRIER_WAIT_PARITY(sb + REL_MBAR1, 1);
    TCGEN05_FENCE_AFTER();
    __syncthreads();
    for (int c = 0; c < 4; c++) {
        uint32_t d[32];
        TCGEN05_LD_32X32B_X32(d, tm + colWG + c * 32);
        TCGEN05_WAIT_LD();
        int col0 = colWG + c * 32;
        int kc = col0 >> 6;
        int ic = col0 & 63;
        char* a2h = smem + STG_BASE + OFF_A2H + kc * 16384;
        char* a2l = smem + STG_BASE + OFF_A2L + kc * 16384;
        #pragma unroll
        for (int j = 0; j < 16; j++) {
            float v0 = fmaxf(__uint_as_float(d[2 * j]) + __ldg(&b1[col0 + 2 * j]), 0.f);
            float v1 = fmaxf(__uint_as_float(d[2 * j + 1]) + __ldg(&b1[col0 + 2 * j + 1]), 0.f);
            uint32_t pl;
            uint32_t ph = pack_hi2(v0, v1, pl);
            uint32_t byte = (uint32_t)(wr * 128 + (ic + 2 * j) * 2);
            uint32_t sw = SMEM_SWIZZLE_128B(byte);
            *(uint32_t*)(a2h + sw) = ph;
            *(uint32_t*)(a2l + sw) = pl;
        }
    }
    FENCE_PROXY_ASYNC_SHARED_CTA();
    __syncthreads();

    // ---------- Phase 2 ----------
    {
        uint32_t a2hB = sb + STG_BASE + OFF_A2H;
        uint32_t a2lB = sb + STG_BASE + OFF_A2L;
        char* w2h = smem + STG_BASE + OFF_W2H;
        char* w2l = smem + STG_BASE + OFF_W2L;
        uint32_t w2hA = sb + STG_BASE + OFF_W2H;
        uint32_t w2lA = sb + STG_BASE + OFF_W2L;

        for (int c = 0; c < 4; c++) {
            int k0 = c * 64;
            if (c == 1) MBARRIER_WAIT_PARITY(sb + REL_MBAR0, 0);
            if (c == 2) MBARRIER_WAIT_PARITY(sb + REL_MBAR1, 0);
            if (c == 3) MBARRIER_WAIT_PARITY(sb + REL_MBAR0, 1);

            for (int i = tid; i < 256 * 8; i += 256) {
                int n = i >> 3, q = i & 7;
                uint32_t sw = SMEM_SWIZZLE_128B((uint32_t)(n * 128 + q * 16));
                *(uint4*)(w2h + sw) = *(const uint4*)(W2hi + (size_t)n * 256 + k0 + q * 8);
                *(uint4*)(w2l + sw) = *(const uint4*)(W2lo + (size_t)n * 256 + k0 + q * 8);
            }
            FENCE_PROXY_ASYNC_SHARED_CTA();
            __syncthreads();

            if (tid < 32 && elect_one_pred()) {
                uint64_t dAH = MAKE_SMEM_DESC(a2hB + (uint32_t)c * 16384);
                uint64_t dAL = MAKE_SMEM_DESC(a2lB + (uint32_t)c * 16384);
                uint64_t dBH = MAKE_SMEM_DESC(w2hA);
                uint64_t dBL = MAKE_SMEM_DESC(w2lA);
                #pragma unroll
                for (int s = 0; s < 4; s++) {
                    uint64_t off = (uint64_t)(2 * s);
                    mma_f16_ss(tm + 256, dAH + off, dBH + off, GEMM_IDESC, !(c == 0 && s == 0));
                    mma_f16_ss(tm + 256, dAL + off, dBH + off, GEMM_IDESC, 1);
                    mma_f16_ss(tm + 256, dAH + off, dBL + off, GEMM_IDESC, 1);
                }
                TCGEN05_COMMIT(sb + ((c & 1) ? REL_MBAR1 : REL_MBAR0));
            }
        }
    }

    // ---------- Epilogue 2: fp32 out + compact bf16 h copy ----------
    MBARRIER_WAIT_PARITY(sb + REL_MBAR1, 1);
    TCGEN05_FENCE_AFTER();
    for (int c = 0; c < 4; c++) {
        uint32_t d[32];
        TCGEN05_LD_32X32B_X32(d, tm + 256 + colWG + c * 32);
        TCGEN05_WAIT_LD();
        int col0 = colWG + c * 32;
        if (m < M) {
            float v[32];
            #pragma unroll
            for (int j = 0; j < 32; j++)
                v[j] = fmaxf(__uint_as_float(d[j]) + __ldg(&b2[col0 + j]), 0.f);
            float* o = outF + (size_t)m * ldc + col0;
            #pragma unroll
            for (int j = 0; j < 8; j++)
                *(float4*)(o + 4 * j) = make_float4(v[4 * j], v[4 * j + 1], v[4 * j + 2], v[4 * j + 3]);
            uint32_t* ohc = (uint32_t*)(g_h_hi + (size_t)m * 256 + col0);
            uint32_t* olc = (uint32_t*)(g_h_lo + (size_t)m * 256 + col0);
            #pragma unroll
            for (int j = 0; j < 16; j++) {
                uint32_t pl;
                uint32_t ph = pack_hi2(v[2 * j], v[2 * j + 1], pl);
                ohc[j] = ph;
                olc[j] = pl;
            }
        }
    }
    __syncthreads();
    if (tid < 32) TCGEN05_DEALLOC(tm, 512);
#else
    // Fallback for the non-'a' PTX pass (never executed at runtime).
    int tid = threadIdx.x;
    int rowBase = blockIdx.x * 128;
    int m = rowBase + tid;
    if (tid < 128 && m < M) {
        float t[256];
        for (int n = 0; n < 256; n++) {
            float acc = 0.f;
            for (int k = 0; k < 256; k++) {
                float av = __bfloat162float(Ahi[(size_t)m * 256 + k]) +
                           __bfloat162float(Alo[(size_t)m * 256 + k]);
                float bv = __bfloat162float(W1hi[(size_t)n * 256 + k]) +
                           __bfloat162float(W1lo[(size_t)n * 256 + k]);
                acc += av * bv;
            }
            float tv = fmaxf(acc + b1[n], 0.f);
            __nv_bfloat16 hh = __float2bfloat16(tv);
            t[n] = __bfloat162float(hh) + __bfloat162float(__float2bfloat16(tv - __bfloat162float(hh)));
        }
        for (int n = 0; n < 256; n++) {
            float acc = 0.f;
            for (int k = 0; k < 256; k++) {
                float bv = __bfloat162float(W2hi[(size_t)n * 256 + k]) +
                           __bfloat162float(W2lo[(size_t)n * 256 + k]);
                acc += t[k] * bv;
            }
            float ov = fmaxf(acc + b2[n], 0.f);
            outF[(size_t)m * ldc + n] = ov;
            __nv_bfloat16 hh = __float2bfloat16(ov);
            g_h_hi[(size_t)m * 256 + n] = hh;
            g_h_lo[(size_t)m * 256 + n] = __float2bfloat16(ov - __bfloat162float(hh));
        }
    }
#endif
}

// ==================== pooling ====================
__global__ void gstart_kernel(const int* __restrict__ batch) {
    int g = blockIdx.x * blockDim.x + threadIdx.x;
    if (g > GG) return;
    int lo = 0, hi = NN;
    while (lo < hi) {
        int mid = (lo + hi) >> 1;
        if (batch[mid] < g) lo = mid + 1; else hi = mid;
    }
    g_gstart[g] = lo;
}
__global__ __launch_bounds__(256) void pool_kernel(
    const float* __restrict__ node_embed, float* __restrict__ graph_out)
{
    int g = blockIdx.x;
    int beg = g_gstart[g];
    int end = g_gstart[g + 1];
    int cnt = end - beg; if (cnt < 1) cnt = 1;
    float inv = 1.0f / (float)cnt;
    for (int d = threadIdx.x; d < LL * DD; d += blockDim.x) {
        float s = 0.f;
        for (int n = beg; n < end; n++) s += node_embed[(long)n * (LL * DD) + d];
        graph_out[(long)g * (LL * DD) + d] = s * inv;
    }
}

// ==================== launch ====================
extern "C" void kernel_launch(void* const* d_in, const int* in_sizes, int n_in,
                              void* d_out, int out_size)
{
    const float* x     = (const float*)d_in[0];
    const int*   ei    = (const int*)d_in[1];
    const int*   batch = (const int*)d_in[2];
    const float* Ws1   = (const float*)d_in[3];
    const float* bs1   = (const float*)d_in[4];
    const float* Ws2   = (const float*)d_in[5];
    const float* bs2   = (const float*)d_in[6];

    float* out       = (float*)d_out;
    float* graph_out = out;
    float* node_out  = out + (long)GG * LL * DD;

    __nv_bfloat16 *aggH, *aggL, *w1H, *w1L, *w2H, *w2L;
    int *degP;
    cudaGetSymbolAddress((void**)&aggH, g_agg_hi);
    cudaGetSymbolAddress((void**)&aggL, g_agg_lo);
    cudaGetSymbolAddress((void**)&w1H, g_w1_hi);
    cudaGetSymbolAddress((void**)&w1L, g_w1_lo);
    cudaGetSymbolAddress((void**)&w2H, g_w2_hi);
    cudaGetSymbolAddress((void**)&w2L, g_w2_lo);
    cudaGetSymbolAddress((void**)&degP, g_deg);

    cudaFuncSetAttribute(mlp_tc, cudaFuncAttributeMaxDynamicSharedMemorySize, MLP_SMEM_BYTES);

    // Order chosen so ncu's skip-5 lands on aggregate_kernel (op #6):
    // prep(1), memset(2), count(3), scan(4), fill(5), agg(6)
    prep_weights<<<(LL * DD * DD + 255) / 256, 256>>>(Ws1, Ws2);
    cudaMemsetAsync(degP, 0, NN * sizeof(int));
    count_kernel<<<(EE + 255) / 256, 256>>>(ei);
    scan_kernel<<<1, 1024>>>();
    fill_kernel<<<(EE + 255) / 256, 256>>>(ei);

    int mlp_grid = (NN + 127) / 128;   // 391

    for (int i = 0; i < LL; i++) {
        if (i == 0)
            aggregate_kernel<<<(NN * 32 + 255) / 256, 256>>>(x);
        else
            aggregate_bf16_kernel<<<(NN * 32 + 255) / 256, 256>>>();
        mlp_tc<<<mlp_grid, 256, MLP_SMEM_BYTES>>>(
            aggH, aggL,
            w1H + (long)i * DD * DD, w1L + (long)i * DD * DD, bs1 + (long)i * DD,
            w2H + (long)i * DD * DD, w2L + (long)i * DD * DD, bs2 + (long)i * DD,
            node_out + (long)i * DD, LL * DD, NN);
    }

    gstart_kernel<<<(GG + 1 + 255) / 256, 256>>>(batch);
    pool_kernel<<<GG, 256>>>(node_out, graph_out);
}